// round 1
// baseline (speedup 1.0000x reference)
#include <cuda_runtime.h>

// ClusteringLayer: q[n,k] = (1/(1+||x_n - c_k||^2)) normalized over k  (ALPHA=1 -> pow exponent = 1)
// d2 = ||x||^2 + ||c||^2 - 2 x.c   (GEMM trick, matches reference)

#define KDIM 512
#define DDIM 512
#define BM   32
#define BK   16
#define NTHREADS 256
#define CS_STRIDE 516  // pad to reduce STS bank conflicts on transpose-store

__device__ float g_c2[KDIM];

// Precompute ||c_k||^2. One block per cluster row, coalesced-ish strided reads.
__global__ void c2_kernel(const float* __restrict__ clusters) {
    int k = blockIdx.x;
    const float* row = clusters + (size_t)k * DDIM;
    float s = 0.f;
    for (int d = threadIdx.x; d < DDIM; d += blockDim.x) {
        float v = row[d];
        s += v * v;
    }
    __shared__ float red[4];
    #pragma unroll
    for (int o = 16; o > 0; o >>= 1) s += __shfl_xor_sync(0xffffffffu, s, o);
    if ((threadIdx.x & 31) == 0) red[threadIdx.x >> 5] = s;
    __syncthreads();
    if (threadIdx.x == 0) g_c2[k] = red[0] + red[1] + red[2] + red[3];
}

// Fused: GEMM (x . c^T) + distance + q + in-CTA row normalization.
// CTA: 32 rows x all 512 cols. Warp w owns rows [4w, 4w+4), all 512 cols.
// Thread (lane) owns cols {lane + 32c : c in 0..15}  -> conflict-free LDS, coalesced STG,
// and row-sum is a single warp shfl reduction.
__global__ __launch_bounds__(NTHREADS, 2)
void cluster_kernel(const float* __restrict__ x,
                    const float* __restrict__ clusters,
                    float* __restrict__ out) {
    __shared__ float cs[BK][CS_STRIDE];   // cs[d][k] transposed cluster tile
    __shared__ float xs[BM][BK];
    __shared__ float x2s[BM];
    __shared__ float xpart[BM][8];
    __shared__ float c2s[KDIM];

    const int tid  = threadIdx.x;
    const int lane = tid & 31;
    const int warp = tid >> 5;
    const long rowBaseG = (long)blockIdx.x * BM;
    const float* xblk = x + rowBaseG * DDIM;

    // Stage c2 into smem
    for (int i = tid; i < KDIM; i += NTHREADS) c2s[i] = g_c2[i];

    // ||x||^2 partials: thread (r, seg) sums 64 contiguous elements of row r
    {
        int r = tid >> 3, seg = tid & 7;
        const float4* p = (const float4*)(xblk + (size_t)r * DDIM + seg * 64);
        float s = 0.f;
        #pragma unroll
        for (int j = 0; j < 16; j++) {
            float4 v = p[j];
            s += v.x * v.x + v.y * v.y + v.z * v.z + v.w * v.w;
        }
        xpart[r][seg] = s;
    }
    __syncthreads();
    if (tid < BM) {
        float s = 0.f;
        #pragma unroll
        for (int j = 0; j < 8; j++) s += xpart[tid][j];
        x2s[tid] = s;
    }

    float acc[4][16];
    #pragma unroll
    for (int r = 0; r < 4; r++)
        #pragma unroll
        for (int c = 0; c < 16; c++) acc[r][c] = 0.f;

    const int rowBase = warp * 4;

    for (int d0 = 0; d0 < DDIM; d0 += BK) {
        __syncthreads();
        // Load cluster tile transposed: cs[d][k] = clusters[k][d0+d]
        // i enumerates (k, dq): 512 rows x 4 float4 quads = 2048 loads
        #pragma unroll
        for (int it = 0; it < 8; it++) {
            int i = tid + it * NTHREADS;
            int k = i >> 2, dq = i & 3;
            float4 v = *(const float4*)(clusters + (size_t)k * DDIM + d0 + dq * 4);
            cs[dq * 4 + 0][k] = v.x;
            cs[dq * 4 + 1][k] = v.y;
            cs[dq * 4 + 2][k] = v.z;
            cs[dq * 4 + 3][k] = v.w;
        }
        // Load x tile: 32 rows x 16 cols = 128 float4
        if (tid < 128) {
            int r = tid >> 2, q = tid & 3;
            float4 v = *(const float4*)(xblk + (size_t)r * DDIM + d0 + q * 4);
            *(float4*)&xs[r][q * 4] = v;
        }
        __syncthreads();

        #pragma unroll
        for (int d = 0; d < BK; d++) {
            float xr[4];
            #pragma unroll
            for (int r = 0; r < 4; r++) xr[r] = xs[rowBase + r][d];
            float cv[16];
            #pragma unroll
            for (int c = 0; c < 16; c++) cv[c] = cs[d][lane + 32 * c];
            #pragma unroll
            for (int r = 0; r < 4; r++)
                #pragma unroll
                for (int c = 0; c < 16; c++)
                    acc[r][c] = fmaf(xr[r], cv[c], acc[r][c]);
        }
    }

    // Epilogue: d2 -> q -> per-row normalize (warp reduce) -> coalesced store
    float c2v[16];
    #pragma unroll
    for (int c = 0; c < 16; c++) c2v[c] = c2s[lane + 32 * c];

    #pragma unroll
    for (int r = 0; r < 4; r++) {
        float x2v = x2s[rowBase + r];
        float rs = 0.f;
        #pragma unroll
        for (int c = 0; c < 16; c++) {
            float d2 = x2v + c2v[c] - 2.f * acc[r][c];
            d2 = fmaxf(d2, 0.f);
            float q = 1.f / (1.f + d2);
            acc[r][c] = q;
            rs += q;
        }
        #pragma unroll
        for (int o = 16; o > 0; o >>= 1) rs += __shfl_xor_sync(0xffffffffu, rs, o);
        float inv = 1.f / rs;
        float* orow = out + (rowBaseG + rowBase + r) * KDIM;
        #pragma unroll
        for (int c = 0; c < 16; c++) orow[lane + 32 * c] = acc[r][c] * inv;
    }
}

extern "C" void kernel_launch(void* const* d_in, const int* in_sizes, int n_in,
                              void* d_out, int out_size) {
    const float* x        = (const float*)d_in[0];
    const float* clusters = (const float*)d_in[1];
    float* out = (float*)d_out;
    int n = in_sizes[0] / DDIM;  // 131072

    c2_kernel<<<KDIM, 128>>>(clusters);
    cluster_kernel<<<n / BM, NTHREADS>>>(x, clusters, out);
}

// round 3
// speedup vs baseline: 5.7395x; 5.7395x over previous
#include <cuda_runtime.h>
#include <cuda_bf16.h>
#include <cstdint>

#define DDIM 512
#define KDIM 512
#define BM   128
#define BN   256     // N-half per GEMM pass
#define BK   32
#define NTH  512
#define NCH  (DDIM / BK)   // 16

// static scratch (no allocations allowed)
__device__ __nv_bfloat16 g_cb[KDIM * DDIM];  // clusters bf16 [K][D]
__device__ float g_c2[KDIM];

// ---- smem layout (bytes) ----
#define ASTRIDE 80           // 32 bf16 = 64B payload, 80B stride (conflict-free ldmatrix)
#define OFF_A   0            // 2 stages * 128*80 = 20480
#define OFF_B   20480u       // 2 stages * 256*80 = 40960
#define OFF_C2  61440u       // 512 * 4
#define OFF_X2  63488u       // 128 * 4
#define OFF_RS  64000u       // 128 * 4
#define OFF_Q   64512u       // 128 * 268 * 4 = 137216
#define QSTR    268
#define SMEM_TOTAL (64512u + 137216u)   // 201728

// ---------------- helpers ----------------
__device__ __forceinline__ uint32_t smem_u32(const void* p) {
    uint32_t a;
    asm("{ .reg .u64 t; cvta.to.shared.u64 t, %1; cvt.u32.u64 %0, t; }" : "=r"(a) : "l"(p));
    return a;
}
__device__ __forceinline__ float frcp(float a) {
    float r; asm("rcp.approx.ftz.f32 %0, %1;" : "=f"(r) : "f"(a)); return r;
}
__device__ __forceinline__ uint32_t pk(float a, float b) {
    __nv_bfloat162 h = __floats2bfloat162_rn(a, b);
    return *reinterpret_cast<uint32_t*>(&h);
}
__device__ __forceinline__ void cp16(uint32_t dst, const void* src) {
    asm volatile("cp.async.cg.shared.global [%0], [%1], 16;"
                 :: "r"(dst), "l"(__cvta_generic_to_global(src)) : "memory");
}
#define CP_COMMIT() asm volatile("cp.async.commit_group;" ::: "memory")
template <int N>
__device__ __forceinline__ void cp_wait() {
    asm volatile("cp.async.wait_group %0;" :: "n"(N) : "memory");
}
__device__ __forceinline__ void ldsm4(uint32_t* r, uint32_t a) {
    asm volatile("ldmatrix.sync.aligned.m8n8.x4.shared.b16 {%0,%1,%2,%3}, [%4];"
                 : "=r"(r[0]), "=r"(r[1]), "=r"(r[2]), "=r"(r[3]) : "r"(a));
}
__device__ __forceinline__ void mma16816(float* c, const uint32_t* a, uint32_t b0, uint32_t b1) {
    asm volatile("mma.sync.aligned.m16n8k16.row.col.f32.bf16.bf16.f32 "
                 "{%0,%1,%2,%3}, {%4,%5,%6,%7}, {%8,%9}, {%0,%1,%2,%3};"
                 : "+f"(c[0]), "+f"(c[1]), "+f"(c[2]), "+f"(c[3])
                 : "r"(a[0]), "r"(a[1]), "r"(a[2]), "r"(a[3]), "r"(b0), "r"(b1));
}

// ---------------- prep: clusters -> bf16, c2 fp32 ----------------
__global__ void prep_kernel(const float* __restrict__ clusters) {
    int k = blockIdx.x, tid = threadIdx.x;
    const float* row = clusters + (size_t)k * DDIM;
    float s = 0.f;
    for (int d = tid; d < DDIM; d += 128) {
        float v = row[d];
        s += v * v;
        g_cb[(size_t)k * DDIM + d] = __float2bfloat16(v);
    }
    #pragma unroll
    for (int o = 16; o > 0; o >>= 1) s += __shfl_xor_sync(0xffffffffu, s, o);
    __shared__ float red[4];
    if ((tid & 31) == 0) red[tid >> 5] = s;
    __syncthreads();
    if (tid == 0) g_c2[k] = red[0] + red[1] + red[2] + red[3];
}

// ---------------- main fused kernel ----------------
__global__ void __launch_bounds__(NTH, 1)
cluster_kernel(const float* __restrict__ x, float* __restrict__ out) {
    extern __shared__ char smem[];
    char*  smA  = smem + OFF_A;
    char*  smB  = smem + OFF_B;
    float* c2s  = (float*)(smem + OFF_C2);
    float* x2s  = (float*)(smem + OFF_X2);
    float* rss  = (float*)(smem + OFF_RS);
    float* qbuf = (float*)(smem + OFF_Q);

    const int tid = threadIdx.x, lane = tid & 31, wid = tid >> 5;
    const int wm = wid & 3, wn = wid >> 2;          // 4 x 4 warp grid, warp tile 32x64
    const long row0 = (long)blockIdx.x * BM;
    const float* xblk = x + row0 * DDIM;

    for (int i = tid; i < KDIM; i += NTH) c2s[i] = g_c2[i];
    if (tid < BM) { x2s[tid] = 0.f; rss[tid] = 0.f; }
    __syncthreads();

    const uint32_t sA = smem_u32(smA), sB = smem_u32(smB);
    const int arow = tid >> 2, apart = tid & 3;     // A loader: 8 floats per thread
    const uint32_t lmr = (lane & 15), lmc = (lane >> 4) * 16;
    float x2acc = 0.f;

    for (int half = 0; half < 2; half++) {
        float acc[2][8][4];
        #pragma unroll
        for (int mt = 0; mt < 2; mt++)
            #pragma unroll
            for (int nt = 0; nt < 8; nt++)
                #pragma unroll
                for (int j = 0; j < 4; j++) acc[mt][nt][j] = 0.f;

        // ---- chunk loaders ----
        auto load_chunk = [&](int c, int s) {
            // A: x fp32 -> bf16
            const float4* ga = (const float4*)(xblk + (size_t)arow * DDIM + c * BK + apart * 8);
            float4 u = ga[0], v = ga[1];
            if (half == 0) {
                x2acc += u.x * u.x + u.y * u.y + u.z * u.z + u.w * u.w;
                x2acc += v.x * v.x + v.y * v.y + v.z * v.z + v.w * v.w;
            }
            uint4 w = make_uint4(pk(u.x, u.y), pk(u.z, u.w), pk(v.x, v.y), pk(v.z, v.w));
            *(uint4*)(smA + s * (BM * ASTRIDE) + arow * ASTRIDE + apart * 16) = w;
            // B: bf16 clusters via cp.async (256 rows x 64B)
            #pragma unroll
            for (int i = 0; i < 2; i++) {
                int idx = tid + i * NTH;
                int brow = idx >> 2, seg = idx & 3;
                uint32_t dst = sB + s * (BN * ASTRIDE) + brow * ASTRIDE + seg * 16;
                const char* src = (const char*)g_cb + ((size_t)(half * BN + brow)) * (DDIM * 2) + c * (BK * 2) + seg * 16;
                cp16(dst, src);
            }
            CP_COMMIT();
        };

        load_chunk(0, 0);
        for (int c = 0; c < NCH; c++) {
            const int s = c & 1;
            if (c + 1 < NCH) { load_chunk(c + 1, s ^ 1); cp_wait<1>(); }
            else cp_wait<0>();
            __syncthreads();

            #pragma unroll
            for (int ks = 0; ks < 2; ks++) {
                uint32_t a0[4], a1[4];
                uint32_t abase = sA + s * (BM * ASTRIDE) + ks * 32 + lmc;
                ldsm4(a0, abase + (wm * 32 + 0  + lmr) * ASTRIDE);
                ldsm4(a1, abase + (wm * 32 + 16 + lmr) * ASTRIDE);
                uint32_t bbase = sB + s * (BN * ASTRIDE) + ks * 32 + lmc;
                #pragma unroll
                for (int bt = 0; bt < 4; bt++) {
                    uint32_t b[4];
                    ldsm4(b, bbase + (wn * 64 + bt * 16 + lmr) * ASTRIDE);
                    // n-tile 2bt uses {b0,b2}; n-tile 2bt+1 uses {b1,b3}
                    mma16816(acc[0][2 * bt + 0], a0, b[0], b[2]);
                    mma16816(acc[0][2 * bt + 1], a0, b[1], b[3]);
                    mma16816(acc[1][2 * bt + 0], a1, b[0], b[2]);
                    mma16816(acc[1][2 * bt + 1], a1, b[1], b[3]);
                }
            }
            __syncthreads();
        }

        if (half == 0) atomicAdd(&x2s[arow], x2acc);
        __syncthreads();   // x2s complete before epilogue reads it

        // ---- epilogue: d2 -> q, row sums ----
        #pragma unroll
        for (int mt = 0; mt < 2; mt++) {
            #pragma unroll
            for (int rr = 0; rr < 2; rr++) {
                const int row = wm * 32 + mt * 16 + (lane >> 2) + rr * 8;
                const float x2v = x2s[row];
                float rsum = 0.f;
                #pragma unroll
                for (int nt = 0; nt < 8; nt++) {
                    const int col = wn * 64 + nt * 8 + (lane & 3) * 2;
                    float c20 = c2s[half * BN + col], c21 = c2s[half * BN + col + 1];
                    float d0 = fmaxf(fmaf(-2.f, acc[mt][nt][rr * 2 + 0], x2v + c20), 0.f);
                    float d1 = fmaxf(fmaf(-2.f, acc[mt][nt][rr * 2 + 1], x2v + c21), 0.f);
                    float q0 = frcp(1.f + d0), q1 = frcp(1.f + d1);
                    acc[mt][nt][rr * 2 + 0] = q0;
                    acc[mt][nt][rr * 2 + 1] = q1;
                    rsum += q0 + q1;
                }
                rsum += __shfl_xor_sync(0xffffffffu, rsum, 1);
                rsum += __shfl_xor_sync(0xffffffffu, rsum, 2);
                if ((lane & 3) == 0) atomicAdd(&rss[row], rsum);
            }
        }

        if (half == 0) {
            // stage q(half0) in smem
            #pragma unroll
            for (int mt = 0; mt < 2; mt++) {
                const int row = wm * 32 + mt * 16 + (lane >> 2);
                #pragma unroll
                for (int nt = 0; nt < 8; nt++) {
                    const int col = wn * 64 + nt * 8 + (lane & 3) * 2;
                    *(float2*)&qbuf[row * QSTR + col]       = make_float2(acc[mt][nt][0], acc[mt][nt][1]);
                    *(float2*)&qbuf[(row + 8) * QSTR + col] = make_float2(acc[mt][nt][2], acc[mt][nt][3]);
                }
            }
            __syncthreads();
        } else {
            __syncthreads();   // all rowsum atomics done
            // half1 from regs
            #pragma unroll
            for (int mt = 0; mt < 2; mt++) {
                #pragma unroll
                for (int rr = 0; rr < 2; rr++) {
                    const int row = wm * 32 + mt * 16 + (lane >> 2) + rr * 8;
                    const float inv = frcp(rss[row]);
                    float* orow = out + (row0 + row) * KDIM + BN;
                    #pragma unroll
                    for (int nt = 0; nt < 8; nt++) {
                        const int col = wn * 64 + nt * 8 + (lane & 3) * 2;
                        *(float2*)&orow[col] = make_float2(acc[mt][nt][rr * 2 + 0] * inv,
                                                           acc[mt][nt][rr * 2 + 1] * inv);
                    }
                }
            }
            // half0 from qbuf
            {
                const int row = tid >> 2, p = tid & 3;
                const float inv = frcp(rss[row]);
                float* orow = out + (row0 + row) * KDIM;
                #pragma unroll
                for (int j = 0; j < 16; j++) {
                    const int col = p * 4 + j * 16;
                    float4 v = *(const float4*)&qbuf[row * QSTR + col];
                    v.x *= inv; v.y *= inv; v.z *= inv; v.w *= inv;
                    *(float4*)&orow[col] = v;
                }
            }
        }
    }
}

extern "C" void kernel_launch(void* const* d_in, const int* in_sizes, int n_in,
                              void* d_out, int out_size) {
    const float* x        = (const float*)d_in[0];
    const float* clusters = (const float*)d_in[1];
    float* out = (float*)d_out;
    int n = in_sizes[0] / DDIM;   // 131072

    cudaFuncSetAttribute(cluster_kernel, cudaFuncAttributeMaxDynamicSharedMemorySize, SMEM_TOTAL);
    prep_kernel<<<KDIM, 128>>>(clusters);
    cluster_kernel<<<n / BM, NTH, SMEM_TOTAL>>>(x, out);
}

// round 4
// speedup vs baseline: 6.3975x; 1.1146x over previous
#include <cuda_runtime.h>
#include <cuda_bf16.h>
#include <cstdint>

#define DDIM 512
#define KDIM 512
#define BM   128
#define BN   256     // N-half per GEMM pass
#define BK   32
#define NTH  512
#define NCH  (DDIM / BK)   // 16

// static scratch (no allocations allowed)
__device__ __nv_bfloat16 g_cb[KDIM * DDIM];  // clusters bf16 [K][D]
__device__ float g_c2[KDIM];

// ---- smem layout (bytes) ----
#define ASTRIDE 80            // 32 bf16 = 64B payload, 80B stride (conflict-free ldmatrix)
#define ASTAGE  3
#define BSTAGE  2
#define OFF_A   0u            // 3 * 128*80 = 30720
#define OFF_B   30720u        // 2 * 256*80 = 40960 -> 71680
#define OFF_C2  71680u        // 512*4     -> 73728
#define OFF_X2  73728u        // 4*128*4   -> 75776   [apart][row]
#define OFF_RS  75776u        // 4*128*4   -> 77824   [wn][row]
#define OFF_Q   77824u        // 128*268*4 = 137216 -> 215040
#define QSTR    268
#define SMEM_TOTAL 215040u

// ---------------- helpers ----------------
__device__ __forceinline__ float frcp(float a) {
    float r; asm("rcp.approx.ftz.f32 %0, %1;" : "=f"(r) : "f"(a)); return r;
}
__device__ __forceinline__ uint32_t pk(float a, float b) {
    __nv_bfloat162 h = __floats2bfloat162_rn(a, b);
    return *reinterpret_cast<uint32_t*>(&h);
}
__device__ __forceinline__ void cp16(uint32_t dst, const void* src) {
    asm volatile("cp.async.cg.shared.global [%0], [%1], 16;"
                 :: "r"(dst), "l"(__cvta_generic_to_global(src)) : "memory");
}
#define CP_COMMIT() asm volatile("cp.async.commit_group;" ::: "memory")
template <int N>
__device__ __forceinline__ void cp_wait() {
    asm volatile("cp.async.wait_group %0;" :: "n"(N) : "memory");
}
__device__ __forceinline__ void ldsm4(uint32_t* r, uint32_t a) {
    asm volatile("ldmatrix.sync.aligned.m8n8.x4.shared.b16 {%0,%1,%2,%3}, [%4];"
                 : "=r"(r[0]), "=r"(r[1]), "=r"(r[2]), "=r"(r[3]) : "r"(a));
}
__device__ __forceinline__ void mma16816(float* c, const uint32_t* a, uint32_t b0, uint32_t b1) {
    asm volatile("mma.sync.aligned.m16n8k16.row.col.f32.bf16.bf16.f32 "
                 "{%0,%1,%2,%3}, {%4,%5,%6,%7}, {%8,%9}, {%0,%1,%2,%3};"
                 : "+f"(c[0]), "+f"(c[1]), "+f"(c[2]), "+f"(c[3])
                 : "r"(a[0]), "r"(a[1]), "r"(a[2]), "r"(a[3]), "r"(b0), "r"(b1));
}

// ---------------- prep: clusters -> bf16, c2 fp32 ----------------
__global__ void prep_kernel(const float* __restrict__ clusters) {
    int k = blockIdx.x, tid = threadIdx.x;
    const float* row = clusters + (size_t)k * DDIM;
    float s = 0.f;
    for (int d = tid; d < DDIM; d += 128) {
        float v = row[d];
        s += v * v;
        g_cb[(size_t)k * DDIM + d] = __float2bfloat16(v);
    }
    #pragma unroll
    for (int o = 16; o > 0; o >>= 1) s += __shfl_xor_sync(0xffffffffu, s, o);
    __shared__ float red[4];
    if ((tid & 31) == 0) red[tid >> 5] = s;
    __syncthreads();
    if (tid == 0) g_c2[k] = red[0] + red[1] + red[2] + red[3];
}

// ---------------- main fused kernel ----------------
__global__ void __launch_bounds__(NTH, 1)
cluster_kernel(const float* __restrict__ x, float* __restrict__ out) {
    extern __shared__ char smem[];
    char*  smA  = smem + OFF_A;
    char*  smB  = smem + OFF_B;
    float* c2s  = (float*)(smem + OFF_C2);
    float* x2p  = (float*)(smem + OFF_X2);
    float* rs4  = (float*)(smem + OFF_RS);
    float* qbuf = (float*)(smem + OFF_Q);

    const int tid = threadIdx.x, lane = tid & 31, wid = tid >> 5;
    const int wm = wid & 3, wn = wid >> 2;          // 4 x 4 warp grid, warp tile 32x64
    const long row0 = (long)blockIdx.x * BM;
    const float* xblk = x + row0 * DDIM;

    for (int i = tid; i < KDIM; i += NTH) c2s[i] = g_c2[i];

    const uint32_t sA = (uint32_t)__cvta_generic_to_shared(smA);
    const uint32_t sB = (uint32_t)__cvta_generic_to_shared(smB);
    const int arow = tid >> 2, apart = tid & 3;     // A loader: 8 floats per thread
    const uint32_t lmr = (lane & 15), lmc = (lane >> 4) * 16;
    float x2acc = 0.f;

    __syncthreads();   // c2s ready (also first-use barrier before stage writes)

    for (int half = 0; half < 2; half++) {
        float acc[2][8][4];
        #pragma unroll
        for (int mt = 0; mt < 2; mt++)
            #pragma unroll
            for (int nt = 0; nt < 8; nt++)
                #pragma unroll
                for (int j = 0; j < 4; j++) acc[mt][nt][j] = 0.f;

        // A: LDG fp32 -> cvt -> STS (3-stage)
        auto loadA = [&](int c, int s) {
            const float4* ga = (const float4*)(xblk + (size_t)arow * DDIM + c * BK + apart * 8);
            float4 u = ga[0], v = ga[1];
            if (half == 0) {
                x2acc += u.x * u.x + u.y * u.y + u.z * u.z + u.w * u.w;
                x2acc += v.x * v.x + v.y * v.y + v.z * v.z + v.w * v.w;
            }
            uint4 w = make_uint4(pk(u.x, u.y), pk(u.z, u.w), pk(v.x, v.y), pk(v.z, v.w));
            *(uint4*)(smA + s * (BM * ASTRIDE) + arow * ASTRIDE + apart * 16) = w;
        };
        // B: cp.async bf16 (2-stage), one commit group per chunk
        auto loadB = [&](int c, int s) {
            #pragma unroll
            for (int i = 0; i < 2; i++) {
                int idx = tid + i * NTH;
                int brow = idx >> 2, seg = idx & 3;
                uint32_t dst = sB + s * (BN * ASTRIDE) + brow * ASTRIDE + seg * 16;
                const char* src = (const char*)g_cb + (size_t)(half * BN + brow) * (DDIM * 2)
                                  + c * (BK * 2) + seg * 16;
                cp16(dst, src);
            }
            CP_COMMIT();
        };

        // prologue
        loadA(0, 0);
        loadA(1, 1);
        loadB(0, 0);

        #pragma unroll
        for (int c = 0; c < NCH; c++) {
            const int sa = c % ASTAGE;
            const int sb = c & 1;
            cp_wait<0>();        // B chunk c landed
            __syncthreads();     // all warps done with compute(c-1); loads visible
            if (c + 1 < NCH) loadB(c + 1, sb ^ 1);
            if (c + 2 < NCH) loadA(c + 2, (c + 2) % ASTAGE);

            #pragma unroll
            for (int ks = 0; ks < 2; ks++) {
                uint32_t a0[4], a1[4];
                uint32_t abase = sA + sa * (BM * ASTRIDE) + ks * 32 + lmc;
                ldsm4(a0, abase + (wm * 32 + 0  + lmr) * ASTRIDE);
                ldsm4(a1, abase + (wm * 32 + 16 + lmr) * ASTRIDE);
                uint32_t bbase = sB + sb * (BN * ASTRIDE) + ks * 32 + lmc;
                #pragma unroll
                for (int bt = 0; bt < 4; bt++) {
                    uint32_t b[4];
                    ldsm4(b, bbase + (wn * 64 + bt * 16 + lmr) * ASTRIDE);
                    mma16816(acc[0][2 * bt + 0], a0, b[0], b[2]);
                    mma16816(acc[0][2 * bt + 1], a0, b[1], b[3]);
                    mma16816(acc[1][2 * bt + 0], a1, b[0], b[2]);
                    mma16816(acc[1][2 * bt + 1], a1, b[1], b[3]);
                }
            }
        }

        if (half == 0) x2p[apart * 128 + arow] = x2acc;  // [apart][row], plain store
        __syncthreads();   // x2 ready; also guards stage-buffer reuse next half

        // ---- epilogue: d2 -> q, row sums (plain per-warp slots, no atomics) ----
        #pragma unroll
        for (int mt = 0; mt < 2; mt++) {
            #pragma unroll
            for (int rr = 0; rr < 2; rr++) {
                const int row = wm * 32 + mt * 16 + (lane >> 2) + rr * 8;
                const float x2v = x2p[row] + x2p[128 + row] + x2p[256 + row] + x2p[384 + row];
                float rsum = 0.f;
                #pragma unroll
                for (int nt = 0; nt < 8; nt++) {
                    const int col = wn * 64 + nt * 8 + (lane & 3) * 2;
                    float c20 = c2s[half * BN + col], c21 = c2s[half * BN + col + 1];
                    float d0 = fmaxf(fmaf(-2.f, acc[mt][nt][rr * 2 + 0], x2v + c20), 0.f);
                    float d1 = fmaxf(fmaf(-2.f, acc[mt][nt][rr * 2 + 1], x2v + c21), 0.f);
                    float q0 = frcp(1.f + d0), q1 = frcp(1.f + d1);
                    acc[mt][nt][rr * 2 + 0] = q0;
                    acc[mt][nt][rr * 2 + 1] = q1;
                    rsum += q0 + q1;
                }
                rsum += __shfl_xor_sync(0xffffffffu, rsum, 1);
                rsum += __shfl_xor_sync(0xffffffffu, rsum, 2);
                if ((lane & 3) == 0) {
                    float prev = half ? rs4[wn * 128 + row] : 0.f;
                    rs4[wn * 128 + row] = prev + rsum;   // same thread both halves: no race
                }
            }
        }

        if (half == 0) {
            // stage q(half0) in smem
            #pragma unroll
            for (int mt = 0; mt < 2; mt++) {
                const int row = wm * 32 + mt * 16 + (lane >> 2);
                #pragma unroll
                for (int nt = 0; nt < 8; nt++) {
                    const int col = wn * 64 + nt * 8 + (lane & 3) * 2;
                    *(float2*)&qbuf[row * QSTR + col]       = make_float2(acc[mt][nt][0], acc[mt][nt][1]);
                    *(float2*)&qbuf[(row + 8) * QSTR + col] = make_float2(acc[mt][nt][2], acc[mt][nt][3]);
                }
            }
            __syncthreads();   // qbuf done; stage buffers free for half1
        } else {
            __syncthreads();   // all rs4 stores done
            // half1 from regs
            #pragma unroll
            for (int mt = 0; mt < 2; mt++) {
                #pragma unroll
                for (int rr = 0; rr < 2; rr++) {
                    const int row = wm * 32 + mt * 16 + (lane >> 2) + rr * 8;
                    const float inv = frcp(rs4[row] + rs4[128 + row] + rs4[256 + row] + rs4[384 + row]);
                    float* orow = out + (row0 + row) * KDIM + BN;
                    #pragma unroll
                    for (int nt = 0; nt < 8; nt++) {
                        const int col = wn * 64 + nt * 8 + (lane & 3) * 2;
                        *(float2*)&orow[col] = make_float2(acc[mt][nt][rr * 2 + 0] * inv,
                                                           acc[mt][nt][rr * 2 + 1] * inv);
                    }
                }
            }
            // half0 from qbuf
            {
                const int row = tid >> 2, p = tid & 3;
                const float inv = frcp(rs4[row] + rs4[128 + row] + rs4[256 + row] + rs4[384 + row]);
                float* orow = out + (row0 + row) * KDIM;
                #pragma unroll
                for (int j = 0; j < 16; j++) {
                    const int col = p * 4 + j * 16;
                    float4 v = *(const float4*)&qbuf[row * QSTR + col];
                    v.x *= inv; v.y *= inv; v.z *= inv; v.w *= inv;
                    *(float4*)&orow[col] = v;
                }
            }
        }
    }
}

extern "C" void kernel_launch(void* const* d_in, const int* in_sizes, int n_in,
                              void* d_out, int out_size) {
    const float* x        = (const float*)d_in[0];
    const float* clusters = (const float*)d_in[1];
    float* out = (float*)d_out;
    int n = in_sizes[0] / DDIM;   // 131072

    cudaFuncSetAttribute(cluster_kernel, cudaFuncAttributeMaxDynamicSharedMemorySize, SMEM_TOTAL);
    prep_kernel<<<KDIM, 128>>>(clusters);
    cluster_kernel<<<n / BM, NTH, SMEM_TOTAL>>>(x, out);
}